// round 5
// baseline (speedup 1.0000x reference)
#include <cuda_runtime.h>
#include <cuda_fp16.h>

#define B 32
#define R 5
#define C 100
#define N 101
#define H 128
#define E 5
#define F 13      // 8 + R
#define TN 8      // nodes per einsum-CTA
#define NT 13     // ceil(N / TN)

// ---------------- scratch (device globals; no allocations allowed) ----------
__device__ __half g_pemb[(size_t)B * N * C * H];   // 82.7 MB, fp16
__device__ float  g_pres[(size_t)B * C * N];       // presence [B,C,N]
__device__ float  g_fx  [(size_t)B * N * H];       // fx1 then fx2
__device__ float  g_ua  [(size_t)B * N * H];       // message-passing state
__device__ float  g_l   [(size_t)B * N * H];       // einsum output

__device__ __forceinline__ float tanh_fast(float x) {
    float y;
    asm("tanh.approx.f32 %0, %1;" : "=f"(y) : "f"(x));
    return y;
}

// ---------------- features: x -> fx1, u = relu(fx1 + bl1) -------------------
__global__ void k_features(const float* __restrict__ ap, const float* __restrict__ act,
                           const float* __restrict__ xa, const float* __restrict__ xb,
                           const float* __restrict__ coord, const float* __restrict__ avail,
                           const float* __restrict__ wx1, const float* __restrict__ bx1,
                           const float* __restrict__ bl1)
{
    int b = blockIdx.x / N, n = blockIdx.x % N;
    __shared__ float xs[F];
    int tid = threadIdx.x;
    if (tid < 5) {
        float s = 0.f;
        #pragma unroll
        for (int r = 0; r < R; r++) {
            int idx = (b * R + r) * N + n;
            float a = ap[idx] + act[idx];
            s = fmaf(a, xa[idx * R + tid], s);
        }
        xs[tid] = s;
    } else if (tid < 10) {
        xs[tid] = xb[(b * N + n) * 5 + tid - 5];
    } else if (tid < 12) {
        xs[tid] = coord[(b * N + n) * 2 + tid - 10];
    } else if (tid == 12) {
        xs[12] = avail[b * N + n];
    }
    __syncthreads();
    int h = tid;
    float acc = bx1[h];
    #pragma unroll
    for (int k = 0; k < F; k++) acc = fmaf(xs[k], wx1[k * H + h], acc);
    int o = (b * N + n) * H + h;
    g_fx[o] = acc;
    g_ua[o] = fmaxf(acc + bl1[h], 0.f);
}

// ---------------- presence head: softmax over n per (b,c) -------------------
__global__ void k_presence(const float* __restrict__ edge, const float* __restrict__ avail,
                           const float* __restrict__ w1p, const float* __restrict__ b1p,
                           const float* __restrict__ w2p, const float* __restrict__ b2p)
{
    int b = blockIdx.x / C, c = blockIdx.x % C;
    __shared__ float w1s[E * H], b1s[H], w2s[H], lg[N], red[H];
    int tid = threadIdx.x;
    for (int i = tid; i < E * H; i += H) w1s[i] = w1p[i];
    b1s[tid] = b1p[tid];
    w2s[tid] = w2p[tid];
    __syncthreads();

    float lgv = -3.4e38f;
    if (tid < N) {
        int n = tid;
        const float* e5 = edge + ((size_t)(b * C + c) * N + n) * E;
        float e0 = e5[0], e1 = e5[1], e2 = e5[2], e3 = e5[3], e4 = e5[4];
        float s = 0.f;
        #pragma unroll 4
        for (int h = 0; h < H; h++) {
            float a = b1s[h];
            a = fmaf(e0, w1s[h], a);
            a = fmaf(e1, w1s[H + h], a);
            a = fmaf(e2, w1s[2 * H + h], a);
            a = fmaf(e3, w1s[3 * H + h], a);
            a = fmaf(e4, w1s[4 * H + h], a);
            s = fmaf(fmaxf(a, 0.f), w2s[h], s);
        }
        s = s + b2p[0];                  // TAU = 1
        float m = avail[b * N + n];
        if (n == c || n == N - 1) m = 0.f;
        lgv = s * m - (1.f - m) * 1e10f;
        lg[n] = lgv;
    }
    red[tid] = lgv;
    __syncthreads();
    for (int s2 = 64; s2 > 0; s2 >>= 1) {
        if (tid < s2) red[tid] = fmaxf(red[tid], red[tid + s2]);
        __syncthreads();
    }
    float mx = red[0];
    __syncthreads();
    float p = 0.f;
    if (tid < N) p = __expf(lg[tid] - mx);
    red[tid] = p;
    __syncthreads();
    for (int s2 = 64; s2 > 0; s2 >>= 1) {
        if (tid < s2) red[tid] += red[tid + s2];
        __syncthreads();
    }
    float inv = 1.f / red[0];
    if (tid < N) {
        float availc = avail[b * N + c];
        g_pres[(size_t)(b * C + c) * N + tid] = availc * p * inv;
    }
}

// ---------------- pemb = presence * tanh(edge @ we + be), fp16 --------------
// block 128: h2 = tid&63 (h pair), co = tid>>6 (c parity). half2 stores.
__global__ void k_pemb(const float* __restrict__ edge, const float* __restrict__ we,
                       const float* __restrict__ be)
{
    int b = blockIdx.x / N, n = blockIdx.x % N;
    __shared__ float2 wes2[E * 64];
    __shared__ float2 bes2[64];
    __shared__ float es[C * E], ps[C];
    int tid = threadIdx.x;
    if (tid < 64) {
        #pragma unroll
        for (int e = 0; e < E; e++)
            wes2[e * 64 + tid] = make_float2(we[e * H + 2 * tid], we[e * H + 2 * tid + 1]);
        bes2[tid] = make_float2(be[2 * tid], be[2 * tid + 1]);
    }
    for (int i = tid; i < C * E; i += 128) {
        int c = i / E, e = i % E;
        es[i] = edge[((size_t)(b * C + c) * N + n) * E + e];
    }
    for (int i = tid; i < C; i += 128) ps[i] = g_pres[(size_t)(b * C + i) * N + n];
    __syncthreads();

    int h2 = tid & 63, co = tid >> 6;
    float2 bb = bes2[h2];
    __half2* out = (__half2*)g_pemb + ((size_t)(b * N + n) * C) * 64 + h2;
    for (int c = co; c < C; c += 2) {
        const float* e5 = es + c * E;
        float a0 = bb.x, a1 = bb.y;
        #pragma unroll
        for (int e = 0; e < E; e++) {
            float2 w = wes2[e * 64 + h2];
            a0 = fmaf(e5[e], w.x, a0);
            a1 = fmaf(e5[e], w.y, a1);
        }
        float p = ps[c];
        out[(size_t)c * 64] = __floats2half2_rn(p * tanh_fast(a0), p * tanh_fast(a1));
    }
}

// ---------------- einsum: l[b,n,h] = sum_c pemb[b,n,c,h] * u[b,c,h] ---------
// High occupancy: smem = u tile only (51.2 KB -> 4 CTAs/SM).
__global__ void k_einsum()
{
    int b = blockIdx.x / NT, nt = blockIdx.x % NT;
    extern __shared__ float2 us[];          // C*64 float2 = 51200 B
    int tid = threadIdx.x;                  // 512

    const float2* u2 = (const float2*)g_ua + (size_t)b * N * 64;
    for (int i = tid; i < C * 64; i += TN * 64) us[i] = u2[i];
    __syncthreads();

    int h2 = tid & 63, nl = tid >> 6;
    int n = nt * TN + nl;
    if (n >= N) return;

    const __half2* pp = (const __half2*)g_pemb + ((size_t)(b * N + n) * C) * 64 + h2;
    float ax0 = 0.f, ay0 = 0.f, ax1 = 0.f, ay1 = 0.f;
    #pragma unroll 2
    for (int c = 0; c < C; c += 2) {
        float2 p0 = __half22float2(pp[(size_t)c * 64]);
        float2 p1 = __half22float2(pp[(size_t)(c + 1) * 64]);
        float2 u0 = us[c * 64 + h2];
        float2 u1 = us[(c + 1) * 64 + h2];
        ax0 = fmaf(p0.x, u0.x, ax0);
        ay0 = fmaf(p0.y, u0.y, ay0);
        ax1 = fmaf(p1.x, u1.x, ax1);
        ay1 = fmaf(p1.y, u1.y, ay1);
    }
    float2 r;
    r.x = ax0 + ax1;
    r.y = ay0 + ay1;
    ((float2*)g_l)[(size_t)(b * N + n) * 64 + h2] = r;
}

// ---------------- u = relu(l @ wl + bl + fx) --------------------------------
__global__ void k_lgemm(const float* __restrict__ wl, const float* __restrict__ bl)
{
    int b = blockIdx.x >> 2, q = blockIdx.x & 3;
    extern __shared__ char sm[];
    float* wls = (float*)sm;                 // H*H = 64 KB
    float* ls  = (float*)(sm + H * H * 4);   // 2*H
    int tid = threadIdx.x;                   // 256
    const float4* w4 = (const float4*)wl;
    float4* s4 = (float4*)wls;
    for (int i = tid; i < H * H / 4; i += 256) s4[i] = w4[i];
    int h = tid & 127, nl = tid >> 7;
    for (int j = 0; j < 26; j += 2) {
        int n = q * 26 + j + nl;
        __syncthreads();
        if (n < N) ls[nl * H + h] = g_l[(b * N + n) * H + h];
        __syncthreads();
        if (n < N) {
            float acc = bl[h] + g_fx[(b * N + n) * H + h];
            #pragma unroll 8
            for (int hp = 0; hp < H; hp++)
                acc = fmaf(ls[nl * H + hp], wls[hp * H + h], acc);
            g_ua[(b * N + n) * H + h] = fmaxf(acc, 0.f);
        }
    }
}

// ---------------- fx2 = u@wx2+bx2; gamma_init = relu(fx2+bl2) ---------------
__global__ void k_fx2(const float* __restrict__ wx2, const float* __restrict__ bx2,
                      const float* __restrict__ bl2)
{
    int b = blockIdx.x >> 2, q = blockIdx.x & 3;
    extern __shared__ char sm[];
    float* wxs = (float*)sm;                 // H*H
    float* ur  = (float*)(sm + H * H * 4);   // 2*H
    int tid = threadIdx.x;                   // 256
    const float4* w4 = (const float4*)wx2;
    float4* s4 = (float4*)wxs;
    for (int i = tid; i < H * H / 4; i += 256) s4[i] = w4[i];
    int h = tid & 127, nl = tid >> 7;
    for (int j = 0; j < 26; j += 2) {
        int n = q * 26 + j + nl;
        __syncthreads();
        if (n < N) ur[nl * H + h] = g_ua[(b * N + n) * H + h];
        __syncthreads();
        if (n < N) {
            float acc = bx2[h];
            #pragma unroll 8
            for (int hp = 0; hp < H; hp++)
                acc = fmaf(ur[nl * H + hp], wxs[hp * H + h], acc);
            int idx = (b * N + n) * H + h;
            g_fx[idx] = acc;
            g_ua[idx] = fmaxf(acc + bl2[h], 0.f);
        }
    }
}

// ---------------- Q readout --------------------------------------------------
__global__ void k_reduce(const float* __restrict__ avail, const float* __restrict__ wQ,
                         float* __restrict__ out)
{
    int b = blockIdx.x;
    int h = threadIdx.x;
    float s = 0.f;
    for (int n = 0; n < N; n++)
        s = fmaf(g_ua[(b * N + n) * H + h], avail[b * N + n], s);
    s *= wQ[h];
    __shared__ float red[H];
    red[h] = s;
    __syncthreads();
    for (int s2 = 64; s2 > 0; s2 >>= 1) {
        if (h < s2) red[h] += red[h + s2];
        __syncthreads();
    }
    if (h == 0) out[b] = red[0];
}

// ---------------- launch -----------------------------------------------------
extern "C" void kernel_launch(void* const* d_in, const int* in_sizes, int n_in,
                              void* d_out, int out_size)
{
    const float* ap    = (const float*)d_in[0];
    const float* act   = (const float*)d_in[1];
    const float* xa    = (const float*)d_in[2];
    const float* xb    = (const float*)d_in[3];
    const float* coord = (const float*)d_in[4];
    const float* edge  = (const float*)d_in[5];
    const float* avail = (const float*)d_in[6];
    const float* w1p   = (const float*)d_in[7];
    const float* b1p   = (const float*)d_in[8];
    const float* w2p   = (const float*)d_in[9];
    const float* b2p   = (const float*)d_in[10];
    const float* wx1   = (const float*)d_in[11];
    const float* bx1   = (const float*)d_in[12];
    const float* we1   = (const float*)d_in[13];
    const float* be1   = (const float*)d_in[14];
    const float* wl1   = (const float*)d_in[15];
    const float* bl1   = (const float*)d_in[16];
    const float* wx2   = (const float*)d_in[17];
    const float* bx2   = (const float*)d_in[18];
    const float* we2   = (const float*)d_in[19];
    const float* be2   = (const float*)d_in[20];
    const float* wl2   = (const float*)d_in[21];
    const float* bl2   = (const float*)d_in[22];
    const float* wQ    = (const float*)d_in[23];
    float* out = (float*)d_out;

    const int es_smem = C * 64 * 8;                 // 51200 B
    const int gm_smem = H * H * 4 + 2 * H * 4;      // 66560 B
    cudaFuncSetAttribute(k_einsum, cudaFuncAttributeMaxDynamicSharedMemorySize, es_smem);
    cudaFuncSetAttribute(k_lgemm,  cudaFuncAttributeMaxDynamicSharedMemorySize, gm_smem);
    cudaFuncSetAttribute(k_fx2,    cudaFuncAttributeMaxDynamicSharedMemorySize, gm_smem);

    k_features<<<B * N, H>>>(ap, act, xa, xb, coord, avail, wx1, bx1, bl1);
    k_presence<<<B * C, H>>>(edge, avail, w1p, b1p, w2p, b2p);

    // round 1 (iteration 1 folded into k_features init; 4 full sweeps)
    k_pemb<<<B * N, 128>>>(edge, we1, be1);
    for (int t = 0; t < 4; t++) {
        k_einsum<<<B * NT, TN * 64, es_smem>>>();
        k_lgemm<<<B * 4, 256, gm_smem>>>(wl1, bl1);
    }

    // round 2
    k_fx2<<<B * 4, 256, gm_smem>>>(wx2, bx2, bl2);
    k_pemb<<<B * N, 128>>>(edge, we2, be2);
    for (int t = 0; t < 4; t++) {
        k_einsum<<<B * NT, TN * 64, es_smem>>>();
        k_lgemm<<<B * 4, 256, gm_smem>>>(wl2, bl2);
    }

    k_reduce<<<B, H>>>(avail, wQ, out);
}

// round 7
// speedup vs baseline: 1.6103x; 1.6103x over previous
#include <cuda_runtime.h>
#include <cuda_fp16.h>

#define B 32
#define R 5
#define C 100
#define C2 50     // c-split half
#define N 101
#define NPAD 104
#define H 128
#define E 5
#define F 13      // 8 + R
#define TN 8      // nodes per tile
#define NT 13     // ceil(N / TN)

// ---------------- scratch (device globals; no allocations allowed) ----------
__device__ __half g_pemb[(size_t)B * N * C * H];       // 82.7 MB, fp16
__device__ float  g_pres[(size_t)B * C * N];           // presence [B,C,N]
__device__ float  g_fx  [(size_t)B * N * H];           // fx1 then fx2
__device__ float  g_ua  [(size_t)B * N * H];           // message-passing state
__device__ float  g_l   [2 * (size_t)B * NPAD * H];    // einsum partials (2 c-halves)

__device__ __forceinline__ float tanh_fast(float x) {
    float y;
    asm("tanh.approx.f32 %0, %1;" : "=f"(y) : "f"(x));
    return y;
}

// ---------------- features: x -> fx1, u = relu(fx1 + bl1) -------------------
__global__ void k_features(const float* __restrict__ ap, const float* __restrict__ act,
                           const float* __restrict__ xa, const float* __restrict__ xb,
                           const float* __restrict__ coord, const float* __restrict__ avail,
                           const float* __restrict__ wx1, const float* __restrict__ bx1,
                           const float* __restrict__ bl1)
{
    int b = blockIdx.x / N, n = blockIdx.x % N;
    __shared__ float xs[F];
    int tid = threadIdx.x;
    if (tid < 5) {
        float s = 0.f;
        #pragma unroll
        for (int r = 0; r < R; r++) {
            int idx = (b * R + r) * N + n;
            float a = ap[idx] + act[idx];
            s = fmaf(a, xa[idx * R + tid], s);
        }
        xs[tid] = s;
    } else if (tid < 10) {
        xs[tid] = xb[(b * N + n) * 5 + tid - 5];
    } else if (tid < 12) {
        xs[tid] = coord[(b * N + n) * 2 + tid - 10];
    } else if (tid == 12) {
        xs[12] = avail[b * N + n];
    }
    __syncthreads();
    int h = tid;
    float acc = bx1[h];
    #pragma unroll
    for (int k = 0; k < F; k++) acc = fmaf(xs[k], wx1[k * H + h], acc);
    int o = (b * N + n) * H + h;
    g_fx[o] = acc;
    g_ua[o] = fmaxf(acc + bl1[h], 0.f);
}

// ---------------- presence head: softmax over n per (b,c) -------------------
__global__ void k_presence(const float* __restrict__ edge, const float* __restrict__ avail,
                           const float* __restrict__ w1p, const float* __restrict__ b1p,
                           const float* __restrict__ w2p, const float* __restrict__ b2p)
{
    int b = blockIdx.x / C, c = blockIdx.x % C;
    __shared__ float w1s[E * H], b1s[H], w2s[H], lg[N], red[H];
    int tid = threadIdx.x;
    for (int i = tid; i < E * H; i += H) w1s[i] = w1p[i];
    b1s[tid] = b1p[tid];
    w2s[tid] = w2p[tid];
    __syncthreads();

    float lgv = -3.4e38f;
    if (tid < N) {
        int n = tid;
        const float* e5 = edge + ((size_t)(b * C + c) * N + n) * E;
        float e0 = e5[0], e1 = e5[1], e2 = e5[2], e3 = e5[3], e4 = e5[4];
        float s = 0.f;
        #pragma unroll 4
        for (int h = 0; h < H; h++) {
            float a = b1s[h];
            a = fmaf(e0, w1s[h], a);
            a = fmaf(e1, w1s[H + h], a);
            a = fmaf(e2, w1s[2 * H + h], a);
            a = fmaf(e3, w1s[3 * H + h], a);
            a = fmaf(e4, w1s[4 * H + h], a);
            s = fmaf(fmaxf(a, 0.f), w2s[h], s);
        }
        s = s + b2p[0];                  // TAU = 1
        float m = avail[b * N + n];
        if (n == c || n == N - 1) m = 0.f;
        lgv = s * m - (1.f - m) * 1e10f;
        lg[n] = lgv;
    }
    red[tid] = lgv;
    __syncthreads();
    for (int s2 = 64; s2 > 0; s2 >>= 1) {
        if (tid < s2) red[tid] = fmaxf(red[tid], red[tid + s2]);
        __syncthreads();
    }
    float mx = red[0];
    __syncthreads();
    float p = 0.f;
    if (tid < N) p = __expf(lg[tid] - mx);
    red[tid] = p;
    __syncthreads();
    for (int s2 = 64; s2 > 0; s2 >>= 1) {
        if (tid < s2) red[tid] += red[tid + s2];
        __syncthreads();
    }
    float inv = 1.f / red[0];
    if (tid < N) {
        float availc = avail[b * N + c];
        g_pres[(size_t)(b * C + c) * N + tid] = availc * p * inv;
    }
}

// ---------------- pemb = presence * tanh(edge @ we + be), fp16 --------------
__global__ void k_pemb(const float* __restrict__ edge, const float* __restrict__ we,
                       const float* __restrict__ be)
{
    int b = blockIdx.x / N, n = blockIdx.x % N;
    __shared__ float2 wes2[E * 64];
    __shared__ float2 bes2[64];
    __shared__ float es[C * E], ps[C];
    int tid = threadIdx.x;
    if (tid < 64) {
        #pragma unroll
        for (int e = 0; e < E; e++)
            wes2[e * 64 + tid] = make_float2(we[e * H + 2 * tid], we[e * H + 2 * tid + 1]);
        bes2[tid] = make_float2(be[2 * tid], be[2 * tid + 1]);
    }
    for (int i = tid; i < C * E; i += 128) {
        int c = i / E, e = i % E;
        es[i] = edge[((size_t)(b * C + c) * N + n) * E + e];
    }
    for (int i = tid; i < C; i += 128) ps[i] = g_pres[(size_t)(b * C + i) * N + n];
    __syncthreads();

    int h2 = tid & 63, co = tid >> 6;
    float2 bb = bes2[h2];
    __half2* out = (__half2*)g_pemb + ((size_t)(b * N + n) * C) * 64 + h2;
    for (int c = co; c < C; c += 2) {
        const float* e5 = es + c * E;
        float a0 = bb.x, a1 = bb.y;
        #pragma unroll
        for (int e = 0; e < E; e++) {
            float2 w = wes2[e * 64 + h2];
            a0 = fmaf(e5[e], w.x, a0);
            a1 = fmaf(e5[e], w.y, a1);
        }
        float p = ps[c];
        out[(size_t)c * 64] = __floats2half2_rn(p * tanh_fast(a0), p * tanh_fast(a1));
    }
}

// ---------------- einsum (c-split): l_hf[b,n,h] = sum_{c in half} pemb*u ----
// grid = B*NT*2, block 256: lane = h-quad (0..31), nl = node-in-tile (0..7)
__global__ void k_einsum()
{
    int id = blockIdx.x;
    int hf = id & 1;
    int nt = (id >> 1) % NT;
    int b  = id / (2 * NT);
    extern __shared__ float4 us4[];            // C2*32 float4 = 25600 B
    int tid = threadIdx.x;

    const float4* u4 = (const float4*)g_ua + ((size_t)b * N + hf * C2) * 32;
    for (int i = tid; i < C2 * 32; i += 256) us4[i] = u4[i];
    __syncthreads();

    int lane = tid & 31, nl = tid >> 5;
    int n = nt * TN + nl;
    if (n >= N) return;

    const uint2* pp = (const uint2*)g_pemb +
                      (((size_t)(b * N + n) * C + hf * C2) * 32) + lane;
    float a0 = 0.f, a1 = 0.f, a2 = 0.f, a3 = 0.f;
    #pragma unroll 5
    for (int c = 0; c < C2; c++) {
        uint2 pv = pp[(size_t)c * 32];
        float4 uv = us4[c * 32 + lane];
        float2 plo = __half22float2(*(__half2*)&pv.x);
        float2 phi = __half22float2(*(__half2*)&pv.y);
        a0 = fmaf(plo.x, uv.x, a0);
        a1 = fmaf(plo.y, uv.y, a1);
        a2 = fmaf(phi.x, uv.z, a2);
        a3 = fmaf(phi.y, uv.w, a3);
    }
    float4 r = make_float4(a0, a1, a2, a3);
    ((float4*)g_l)[((size_t)hf * B * NPAD + (size_t)b * NPAD + n) * 32 + lane] = r;
}

// ---------------- u = relu((l0+l1) @ wl + bl + fx), node-parallel -----------
// grid = B*NT, block 256: h2 = h-pair (0..63), ng = node-pair (0..3)
__global__ void k_lgemm(const float* __restrict__ wl, const float* __restrict__ bl)
{
    int b = blockIdx.x / NT, nt = blockIdx.x % NT;
    extern __shared__ char sm[];
    float* wls = (float*)sm;                    // H*H = 64 KB
    float* ls  = (float*)(sm + H * H * 4);      // TN*H = 4 KB
    int tid = threadIdx.x;                      // 256

    const float4* w4 = (const float4*)wl;
    float4* s4 = (float4*)wls;
    #pragma unroll
    for (int i = tid; i < H * H / 4; i += 256) s4[i] = w4[i];
    {
        int nl = tid >> 5, j = tid & 31;
        int n = nt * TN + nl;
        float4 v = make_float4(0.f, 0.f, 0.f, 0.f);
        if (n < N) {
            float4 x = ((const float4*)g_l)[((size_t)b * NPAD + n) * 32 + j];
            float4 y = ((const float4*)g_l)[((size_t)B * NPAD + (size_t)b * NPAD + n) * 32 + j];
            v = make_float4(x.x + y.x, x.y + y.y, x.z + y.z, x.w + y.w);
        }
        ((float4*)ls)[tid] = v;
    }
    __syncthreads();

    int h2 = tid & 63, ng = tid >> 6;
    int nl0 = ng * 2, nl1 = ng * 2 + 1;
    float2 a0 = make_float2(0.f, 0.f), a1 = make_float2(0.f, 0.f);
    const float2* wl2 = (const float2*)wls;
    #pragma unroll 8
    for (int hp = 0; hp < H; hp++) {
        float2 w = wl2[hp * 64 + h2];
        float l0 = ls[nl0 * H + hp];
        float l1 = ls[nl1 * H + hp];
        a0.x = fmaf(l0, w.x, a0.x); a0.y = fmaf(l0, w.y, a0.y);
        a1.x = fmaf(l1, w.x, a1.x); a1.y = fmaf(l1, w.y, a1.y);
    }
    float2 bb = ((const float2*)bl)[h2];
    int n0 = nt * TN + nl0, n1 = nt * TN + nl1;
    if (n0 < N) {
        float2 fx = ((const float2*)g_fx)[((size_t)b * N + n0) * 64 + h2];
        ((float2*)g_ua)[((size_t)b * N + n0) * 64 + h2] =
            make_float2(fmaxf(a0.x + bb.x + fx.x, 0.f), fmaxf(a0.y + bb.y + fx.y, 0.f));
    }
    if (n1 < N) {
        float2 fx = ((const float2*)g_fx)[((size_t)b * N + n1) * 64 + h2];
        ((float2*)g_ua)[((size_t)b * N + n1) * 64 + h2] =
            make_float2(fmaxf(a1.x + bb.x + fx.x, 0.f), fmaxf(a1.y + bb.y + fx.y, 0.f));
    }
}

// ---------------- fx2 = u@wx2+bx2; gamma_init = relu(fx2+bl2) ---------------
// same node-parallel mapping as k_lgemm
__global__ void k_fx2(const float* __restrict__ wx2, const float* __restrict__ bx2,
                      const float* __restrict__ bl2)
{
    int b = blockIdx.x / NT, nt = blockIdx.x % NT;
    extern __shared__ char sm[];
    float* wxs = (float*)sm;                    // H*H
    float* ur  = (float*)(sm + H * H * 4);      // TN*H
    int tid = threadIdx.x;                      // 256

    const float4* w4 = (const float4*)wx2;
    float4* s4 = (float4*)wxs;
    #pragma unroll
    for (int i = tid; i < H * H / 4; i += 256) s4[i] = w4[i];
    {
        int nl = tid >> 5, j = tid & 31;
        int n = nt * TN + nl;
        float4 v = make_float4(0.f, 0.f, 0.f, 0.f);
        if (n < N) v = ((const float4*)g_ua)[((size_t)b * N + n) * 32 + j];
        ((float4*)ur)[tid] = v;
    }
    __syncthreads();

    int h2 = tid & 63, ng = tid >> 6;
    int nl0 = ng * 2, nl1 = ng * 2 + 1;
    float2 a0 = make_float2(0.f, 0.f), a1 = make_float2(0.f, 0.f);
    const float2* wx2s = (const float2*)wxs;
    #pragma unroll 8
    for (int hp = 0; hp < H; hp++) {
        float2 w = wx2s[hp * 64 + h2];
        float u0 = ur[nl0 * H + hp];
        float u1 = ur[nl1 * H + hp];
        a0.x = fmaf(u0, w.x, a0.x); a0.y = fmaf(u0, w.y, a0.y);
        a1.x = fmaf(u1, w.x, a1.x); a1.y = fmaf(u1, w.y, a1.y);
    }
    float2 bx = ((const float2*)bx2)[h2];
    float2 bb = ((const float2*)bl2)[h2];
    int n0 = nt * TN + nl0, n1 = nt * TN + nl1;
    if (n0 < N) {
        float2 fx = make_float2(a0.x + bx.x, a0.y + bx.y);
        ((float2*)g_fx)[((size_t)b * N + n0) * 64 + h2] = fx;
        ((float2*)g_ua)[((size_t)b * N + n0) * 64 + h2] =
            make_float2(fmaxf(fx.x + bb.x, 0.f), fmaxf(fx.y + bb.y, 0.f));
    }
    if (n1 < N) {
        float2 fx = make_float2(a1.x + bx.x, a1.y + bx.y);
        ((float2*)g_fx)[((size_t)b * N + n1) * 64 + h2] = fx;
        ((float2*)g_ua)[((size_t)b * N + n1) * 64 + h2] =
            make_float2(fmaxf(fx.x + bb.x, 0.f), fmaxf(fx.y + bb.y, 0.f));
    }
}

// ---------------- Q readout --------------------------------------------------
__global__ void k_reduce(const float* __restrict__ avail, const float* __restrict__ wQ,
                         float* __restrict__ out)
{
    int b = blockIdx.x;
    int h = threadIdx.x;
    float s = 0.f;
    for (int n = 0; n < N; n++)
        s = fmaf(g_ua[(b * N + n) * H + h], avail[b * N + n], s);
    s *= wQ[h];
    __shared__ float red[H];
    red[h] = s;
    __syncthreads();
    for (int s2 = 64; s2 > 0; s2 >>= 1) {
        if (h < s2) red[h] += red[h + s2];
        __syncthreads();
    }
    if (h == 0) out[b] = red[0];
}

// ---------------- launch -----------------------------------------------------
extern "C" void kernel_launch(void* const* d_in, const int* in_sizes, int n_in,
                              void* d_out, int out_size)
{
    const float* ap    = (const float*)d_in[0];
    const float* act   = (const float*)d_in[1];
    const float* xa    = (const float*)d_in[2];
    const float* xb    = (const float*)d_in[3];
    const float* coord = (const float*)d_in[4];
    const float* edge  = (const float*)d_in[5];
    const float* avail = (const float*)d_in[6];
    const float* w1p   = (const float*)d_in[7];
    const float* b1p   = (const float*)d_in[8];
    const float* w2p   = (const float*)d_in[9];
    const float* b2p   = (const float*)d_in[10];
    const float* wx1   = (const float*)d_in[11];
    const float* bx1   = (const float*)d_in[12];
    const float* we1   = (const float*)d_in[13];
    const float* be1   = (const float*)d_in[14];
    const float* wl1   = (const float*)d_in[15];
    const float* bl1   = (const float*)d_in[16];
    const float* wx2   = (const float*)d_in[17];
    const float* bx2   = (const float*)d_in[18];
    const float* we2   = (const float*)d_in[19];
    const float* be2   = (const float*)d_in[20];
    const float* wl2   = (const float*)d_in[21];
    const float* bl2   = (const float*)d_in[22];
    const float* wQ    = (const float*)d_in[23];
    float* out = (float*)d_out;

    const int es_smem = C2 * 32 * 16;               // 25600 B
    const int gm_smem = H * H * 4 + TN * H * 4;     // 69632 B
    cudaFuncSetAttribute(k_einsum, cudaFuncAttributeMaxDynamicSharedMemorySize, es_smem);
    cudaFuncSetAttribute(k_lgemm,  cudaFuncAttributeMaxDynamicSharedMemorySize, gm_smem);
    cudaFuncSetAttribute(k_fx2,    cudaFuncAttributeMaxDynamicSharedMemorySize, gm_smem);

    k_features<<<B * N, H>>>(ap, act, xa, xb, coord, avail, wx1, bx1, bl1);
    k_presence<<<B * C, H>>>(edge, avail, w1p, b1p, w2p, b2p);

    // round 1 (iteration 1 folded into k_features init; 4 full sweeps)
    k_pemb<<<B * N, 128>>>(edge, we1, be1);
    for (int t = 0; t < 4; t++) {
        k_einsum<<<B * NT * 2, 256, es_smem>>>();
        k_lgemm<<<B * NT, 256, gm_smem>>>(wl1, bl1);
    }

    // round 2
    k_fx2<<<B * NT, 256, gm_smem>>>(wx2, bx2, bl2);
    k_pemb<<<B * N, 128>>>(edge, we2, be2);
    for (int t = 0; t < 4; t++) {
        k_einsum<<<B * NT * 2, 256, es_smem>>>();
        k_lgemm<<<B * NT, 256, gm_smem>>>(wl2, bl2);
    }

    k_reduce<<<B, H>>>(avail, wQ, out);
}